// round 13
// baseline (speedup 1.0000x reference)
#include <cuda_runtime.h>
#include <cuda_fp16.h>
#include <cstdint>

#define USER_NUM 100000
#define ITEM_NUM 50000
#define DIM      64
#define NEDGE    3200000
#define NB       16384
#define SCAN_CHUNK 4096
#define NBU 25   // ceil(100000/4096)
#define NBI 13   // ceil(50000/4096)

// ---------------- scratch (device globals) ----------------------------------
__device__ __half g_embu_h[USER_NUM * DIM];
__device__ __half g_embi_h[ITEM_NUM * DIM];
__device__ __half g_g1u[USER_NUM * DIM];
__device__ __half g_g2u[USER_NUM * DIM];
__device__ __half g_g1i[ITEM_NUM * DIM];
__device__ __half g_g2i[ITEM_NUM * DIM];
__device__ float  g_gcnu[USER_NUM * DIM];
__device__ float  g_gcni[ITEM_NUM * DIM];

__device__ int  g_cnt_u[USER_NUM];
__device__ int  g_cnt_i[ITEM_NUM];
__device__ int  g_rowptr_u[USER_NUM + 1];
__device__ int  g_rowptr_i[ITEM_NUM + 1];
__device__ int  g_bsum_u[32];
__device__ int  g_bsum_i[32];
__device__ int  g_pos_u[NEDGE];   // within-row slot from hist atomic
__device__ int  g_pos_i[NEDGE];
__device__ int2 g_csr_u[NEDGE];
__device__ int2 g_csr_i[NEDGE];

// [0]=bpr_sum, [1]=reg_sum, [2]=lossU dot, [3]=lossI dot
__device__ float g_acc[4];

// ---------------- zero counters ----------------------------------------------
__global__ void zero_kernel() {
    int stride = gridDim.x * blockDim.x;
    for (int i = blockIdx.x * blockDim.x + threadIdx.x; i < USER_NUM; i += stride)
        g_cnt_u[i] = 0;
    for (int i = blockIdx.x * blockDim.x + threadIdx.x; i < ITEM_NUM; i += stride)
        g_cnt_i[i] = 0;
    if (blockIdx.x == 0 && threadIdx.x < 4) g_acc[threadIdx.x] = 0.f;
}

// ---------------- convert embeddings to fp16 (side stream) ---------------------
__global__ void conv_kernel(const float* __restrict__ ue, const float* __restrict__ ie) {
    int stride = gridDim.x * blockDim.x;
    const int nu2 = USER_NUM * DIM / 2;
    const int ni2 = ITEM_NUM * DIM / 2;
    for (int i = blockIdx.x * blockDim.x + threadIdx.x; i < nu2; i += stride) {
        float2 f = reinterpret_cast<const float2*>(ue)[i];
        reinterpret_cast<__half2*>(g_embu_h)[i] = __floats2half2_rn(f.x, f.y);
    }
    for (int i = blockIdx.x * blockDim.x + threadIdx.x; i < ni2; i += stride) {
        float2 f = reinterpret_cast<const float2*>(ie)[i];
        reinterpret_cast<__half2*>(g_embi_h)[i] = __floats2half2_rn(f.x, f.y);
    }
}

// ---------------- histogram + slot assignment: 4 edges/thread -------------------
__global__ void hist_kernel(const int* __restrict__ eu, const int* __restrict__ ei) {
    int t = blockIdx.x * blockDim.x + threadIdx.x;
    if (t >= NEDGE / 4) return;
    int4 u = __ldg(reinterpret_cast<const int4*>(eu) + t);
    int4 v = __ldg(reinterpret_cast<const int4*>(ei) + t);
    int4 pu, pi;
    pu.x = atomicAdd(&g_cnt_u[u.x], 1);
    pu.y = atomicAdd(&g_cnt_u[u.y], 1);
    pu.z = atomicAdd(&g_cnt_u[u.z], 1);
    pu.w = atomicAdd(&g_cnt_u[u.w], 1);
    pi.x = atomicAdd(&g_cnt_i[v.x], 1);
    pi.y = atomicAdd(&g_cnt_i[v.y], 1);
    pi.z = atomicAdd(&g_cnt_i[v.z], 1);
    pi.w = atomicAdd(&g_cnt_i[v.w], 1);
    reinterpret_cast<int4*>(g_pos_u)[t] = pu;
    reinterpret_cast<int4*>(g_pos_i)[t] = pi;
}

// ---------------- merged 3-phase scan ----------------------------------------------
__global__ void scan_partial2() {
    bool isU = blockIdx.x < NBU;
    const int* __restrict__ cnt = isU ? g_cnt_u : g_cnt_i;
    int* __restrict__ bsum      = isU ? g_bsum_u : g_bsum_i;
    int n = isU ? USER_NUM : ITEM_NUM;
    int b = isU ? blockIdx.x : blockIdx.x - NBU;

    __shared__ int sw[8];
    int t = threadIdx.x;
    int base = b * SCAN_CHUNK;
    int s = 0;
    #pragma unroll
    for (int k = 0; k < 16; k++) {
        int i = base + k * 256 + t;
        if (i < n) s += cnt[i];
    }
    #pragma unroll
    for (int off = 16; off; off >>= 1) s += __shfl_xor_sync(0xffffffffu, s, off);
    if ((t & 31) == 0) sw[t >> 5] = s;
    __syncthreads();
    if (t == 0) {
        int tot = 0;
        #pragma unroll
        for (int k = 0; k < 8; k++) tot += sw[k];
        bsum[b] = tot;
    }
}

__global__ void scan_bsum2() {
    int w = threadIdx.x >> 5, lane = threadIdx.x & 31;
    int* bsum = w ? g_bsum_i : g_bsum_u;
    int nb = w ? NBI : NBU;
    int v = (lane < nb) ? bsum[lane] : 0;
    int incl = v;
    #pragma unroll
    for (int off = 1; off < 32; off <<= 1) {
        int y = __shfl_up_sync(0xffffffffu, incl, off);
        if (lane >= off) incl += y;
    }
    if (lane < nb) bsum[lane] = incl - v;
    if (lane == 0) {
        if (w) g_rowptr_i[ITEM_NUM] = NEDGE; else g_rowptr_u[USER_NUM] = NEDGE;
    }
}

__global__ void scan_final2() {
    bool isU = blockIdx.x < NBU;
    const int* __restrict__ cnt  = isU ? g_cnt_u : g_cnt_i;
    int* __restrict__ rowptr     = isU ? g_rowptr_u : g_rowptr_i;
    const int* __restrict__ bsum = isU ? g_bsum_u : g_bsum_i;
    int n = isU ? USER_NUM : ITEM_NUM;
    int b = isU ? blockIdx.x : blockIdx.x - NBU;

    int t = threadIdx.x;
    int base = b * SCAN_CHUNK;
    int idx0 = base + t * 16;
    int v[16];
    int s = 0;
    #pragma unroll
    for (int k = 0; k < 16; k++) {
        int i = idx0 + k;
        v[k] = (i < n) ? cnt[i] : 0;
        s += v[k];
    }
    int lane = t & 31, w = t >> 5;
    int sIncl = s;
    #pragma unroll
    for (int off = 1; off < 32; off <<= 1) {
        int y = __shfl_up_sync(0xffffffffu, sIncl, off);
        if (lane >= off) sIncl += y;
    }
    __shared__ int wsum[8], wpre[8];
    if (lane == 31) wsum[w] = sIncl;
    __syncthreads();
    if (t == 0) {
        int run = 0;
        #pragma unroll
        for (int k = 0; k < 8; k++) { wpre[k] = run; run += wsum[k]; }
    }
    __syncthreads();
    int excl = bsum[b] + wpre[w] + (sIncl - s);
    #pragma unroll
    for (int k = 0; k < 16; k++) {
        int i = idx0 + k;
        if (i < n) { rowptr[i] = excl; excl += v[k]; }
    }
}

// ---------------- scatter: atomic-FREE (uses precomputed slots) --------------------
__global__ void scatter_kernel(const int* __restrict__ eu, const int* __restrict__ ei,
                               const float* __restrict__ ev) {
    int t = blockIdx.x * blockDim.x + threadIdx.x;
    if (t >= NEDGE / 2) return;
    int2  u  = __ldg(reinterpret_cast<const int2*>(eu) + t);
    int2  it = __ldg(reinterpret_cast<const int2*>(ei) + t);
    float2 v = __ldg(reinterpret_cast<const float2*>(ev) + t);
    int2 pu = __ldg(reinterpret_cast<const int2*>(g_pos_u) + t);
    int2 pi = __ldg(reinterpret_cast<const int2*>(g_pos_i) + t);
    int vb0 = __float_as_int(v.x);
    int vb1 = __float_as_int(v.y);
    int bu0 = __ldg(g_rowptr_u + u.x)  + pu.x;
    int bu1 = __ldg(g_rowptr_u + u.y)  + pu.y;
    int bi0 = __ldg(g_rowptr_i + it.x) + pi.x;
    int bi1 = __ldg(g_rowptr_i + it.y) + pi.y;
    g_csr_u[bu0] = make_int2(it.x, vb0);
    g_csr_u[bu1] = make_int2(it.y, vb1);
    g_csr_i[bi0] = make_int2(u.x,  vb0);
    g_csr_i[bi1] = make_int2(u.y,  vb1);
}

// ---------------- SPMM: half gather -> half out (proven body, unchanged) ----------
__global__ void spmm_h2h(const int* __restrict__ rowptr, const int2* __restrict__ csr,
                         const __half* __restrict__ x, __half* __restrict__ out, int nrows) {
    int row  = (blockIdx.x * blockDim.x + threadIdx.x) >> 5;
    int lane = threadIdx.x & 31;
    int lane16 = lane & 15, hw = lane >> 4;
    if (row >= nrows) return;
    int beg = __ldg(rowptr + row), end = __ldg(rowptr + row + 1);

    float4 acc = make_float4(0.f, 0.f, 0.f, 0.f);
    for (int e = beg + hw; e < end; e += 2) {
        int2 cv = __ldg(csr + e);
        float v = __int_as_float(cv.y);
        uint2 raw = __ldg(reinterpret_cast<const uint2*>(x) + (size_t)cv.x * 16 + lane16);
        float2 f0 = __half22float2(*reinterpret_cast<__half2*>(&raw.x));
        float2 f1 = __half22float2(*reinterpret_cast<__half2*>(&raw.y));
        acc.x = fmaf(v, f0.x, acc.x);
        acc.y = fmaf(v, f0.y, acc.y);
        acc.z = fmaf(v, f1.x, acc.z);
        acc.w = fmaf(v, f1.y, acc.w);
    }
    acc.x += __shfl_xor_sync(0xffffffffu, acc.x, 16);
    acc.y += __shfl_xor_sync(0xffffffffu, acc.y, 16);
    acc.z += __shfl_xor_sync(0xffffffffu, acc.z, 16);
    acc.w += __shfl_xor_sync(0xffffffffu, acc.w, 16);
    if (lane < 16) {
        __half2 h0 = __floats2half2_rn(acc.x, acc.y);
        __half2 h1 = __floats2half2_rn(acc.z, acc.w);
        uint2 pk;
        pk.x = *reinterpret_cast<unsigned*>(&h0);
        pk.y = *reinterpret_cast<unsigned*>(&h1);
        reinterpret_cast<uint2*>(out)[(size_t)row * 16 + lane16] = pk;
    }
}

// ---------------- hop 3 fused: half gather + gcn combine + self-distill -------------
__global__ void spmm3_fused(const int* __restrict__ rowptr, const int2* __restrict__ csr,
                            const __half* __restrict__ xg,
                            const float* __restrict__ emb,
                            const __half* __restrict__ g1,
                            const __half* __restrict__ g2,
                            const float* __restrict__ oldE,
                            const float* __restrict__ nvec,
                            float* __restrict__ gcn,
                            float* __restrict__ accslot,
                            int nrows) {
    int warpInBlk = threadIdx.x >> 5;
    int row  = (blockIdx.x * blockDim.x + threadIdx.x) >> 5;
    int lane = threadIdx.x & 31;
    int lane16 = lane & 15, hw = lane >> 4;

    __shared__ float sm[8];
    float contrib = 0.f;

    if (row < nrows) {
        int beg = __ldg(rowptr + row), end = __ldg(rowptr + row + 1);
        float4 acc = make_float4(0.f, 0.f, 0.f, 0.f);
        for (int e = beg + hw; e < end; e += 2) {
            int2 cv = __ldg(csr + e);
            float v = __int_as_float(cv.y);
            uint2 raw = __ldg(reinterpret_cast<const uint2*>(xg) + (size_t)cv.x * 16 + lane16);
            float2 f0 = __half22float2(*reinterpret_cast<__half2*>(&raw.x));
            float2 f1 = __half22float2(*reinterpret_cast<__half2*>(&raw.y));
            acc.x = fmaf(v, f0.x, acc.x);
            acc.y = fmaf(v, f0.y, acc.y);
            acc.z = fmaf(v, f1.x, acc.z);
            acc.w = fmaf(v, f1.y, acc.w);
        }
        acc.x += __shfl_xor_sync(0xffffffffu, acc.x, 16);
        acc.y += __shfl_xor_sync(0xffffffffu, acc.y, 16);
        acc.z += __shfl_xor_sync(0xffffffffu, acc.z, 16);
        acc.w += __shfl_xor_sync(0xffffffffu, acc.w, 16);

        float sq = 0.f;
        if (lane < 16) {
            size_t rb = (size_t)row * DIM;
            float4 ee = __ldg(reinterpret_cast<const float4*>(emb + rb) + lane16);
            uint2 r1 = __ldg(reinterpret_cast<const uint2*>(g1) + (size_t)row * 16 + lane16);
            uint2 r2 = __ldg(reinterpret_cast<const uint2*>(g2) + (size_t)row * 16 + lane16);
            float2 g1a = __half22float2(*reinterpret_cast<__half2*>(&r1.x));
            float2 g1b = __half22float2(*reinterpret_cast<__half2*>(&r1.y));
            float2 g2a = __half22float2(*reinterpret_cast<__half2*>(&r2.x));
            float2 g2b = __half22float2(*reinterpret_cast<__half2*>(&r2.y));
            const float c2 = 1.f / 3.f;
            float4 gv;
            gv.x = ee.x + 0.5f * g1a.x + c2 * g2a.x + 0.25f * acc.x;
            gv.y = ee.y + 0.5f * g1a.y + c2 * g2a.y + 0.25f * acc.y;
            gv.z = ee.z + 0.5f * g1b.x + c2 * g2b.x + 0.25f * acc.z;
            gv.w = ee.w + 0.5f * g1b.y + c2 * g2b.y + 0.25f * acc.w;
            reinterpret_cast<float4*>(gcn + rb)[lane16] = gv;

            float4 ov = __ldg(reinterpret_cast<const float4*>(oldE + rb) + lane16);
            float dx = ov.x - gv.x, dy = ov.y - gv.y, dz = ov.z - gv.z, dw = ov.w - gv.w;
            sq = dx * dx + dy * dy + dz * dz + dw * dw;
        }
        #pragma unroll
        for (int off = 16; off; off >>= 1) sq += __shfl_xor_sync(0xffffffffu, sq, off);
        if (lane == 0) contrib = sqrtf(sq) * __ldg(nvec + row);
    }

    if (lane == 0) sm[warpInBlk] = contrib;
    __syncthreads();
    if (threadIdx.x == 0) {
        float v = 0.f;
        #pragma unroll
        for (int k = 0; k < 8; k++) v += sm[k];
        atomicAdd(accslot, v);
    }
}

// ---------------- BPR loss ---------------------------------------------------------
__global__ void bpr_kernel(const int* __restrict__ user,
                           const int* __restrict__ iti,
                           const int* __restrict__ itj) {
    int warp = threadIdx.x >> 5;
    int lane = threadIdx.x & 31;
    int b = blockIdx.x * 8 + warp;

    float lbpr = 0.f, lreg = 0.f;
    if (b < NB) {
        int uu = user[b], a = iti[b], c = itj[b];
        float2 u2 = reinterpret_cast<const float2*>(g_gcnu + (size_t)uu * DIM)[lane];
        float2 x1 = reinterpret_cast<const float2*>(g_gcni + (size_t)a  * DIM)[lane];
        float2 x2 = reinterpret_cast<const float2*>(g_gcni + (size_t)c  * DIM)[lane];
        float pi = u2.x * x1.x + u2.y * x1.y;
        float pj = u2.x * x2.x + u2.y * x2.y;
        float rg = u2.x * u2.x + u2.y * u2.y
                 + x1.x * x1.x + x1.y * x1.y
                 + x2.x * x2.x + x2.y * x2.y;
        #pragma unroll
        for (int off = 16; off; off >>= 1) {
            pi += __shfl_xor_sync(0xffffffffu, pi, off);
            pj += __shfl_xor_sync(0xffffffffu, pj, off);
            rg += __shfl_xor_sync(0xffffffffu, rg, off);
        }
        if (lane == 0) {
            float x = pi - pj;
            lbpr = fmaxf(-x, 0.f) + log1pf(expf(-fabsf(x)));
            lreg = rg;
        }
    }
    __shared__ float s1[8], s2[8];
    if (lane == 0) { s1[warp] = lbpr; s2[warp] = lreg; }
    __syncthreads();
    if (threadIdx.x == 0) {
        float a = 0.f, r = 0.f;
        #pragma unroll
        for (int k = 0; k < 8; k++) { a += s1[k]; r += s2[k]; }
        atomicAdd(&g_acc[0], a);
        atomicAdd(&g_acc[1], r);
    }
}

// ---------------- finalize -------------------------------------------------------------
__global__ void finalize_kernel(float* __restrict__ out) {
    if (threadIdx.x == 0) {
        float bpr = g_acc[0] / (float)NB;
        float reg = 1e-4f * (g_acc[1] / (float)NB);
        float ls  = g_acc[2] / (float)USER_NUM + g_acc[3] / (float)ITEM_NUM;
        out[0] = bpr + reg;
        out[1] = 100.f * ls;
        out[2] = 1.f;
        out[3] = 1.f;
    }
}

// ---------------- launch ------------------------------------------------------------------
extern "C" void kernel_launch(void* const* d_in, const int* in_sizes, int n_in,
                              void* d_out, int out_size) {
    const int*   user     = (const int*)d_in[0];
    const int*   item_i   = (const int*)d_in[1];
    const int*   item_j   = (const int*)d_in[2];
    const int*   edge_u   = (const int*)d_in[3];
    const int*   edge_i   = (const int*)d_in[4];
    const float* edge_val = (const float*)d_in[5];
    const float* user_emb = (const float*)d_in[6];
    const float* item_emb = (const float*)d_in[7];
    const float* old_U    = (const float*)d_in[8];
    const float* old_I    = (const float*)d_in[9];
    const float* n_U      = (const float*)d_in[10];
    const float* n_I      = (const float*)d_in[11];
    float* out = (float*)d_out;

    __half *p_embu, *p_embi, *p_g1u, *p_g2u, *p_g1i, *p_g2i;
    float  *p_gcnu, *p_gcni, *p_acc;
    int    *p_rpu, *p_rpi;
    int2   *p_csru, *p_csri;
    cudaGetSymbolAddress((void**)&p_embu, g_embu_h);
    cudaGetSymbolAddress((void**)&p_embi, g_embi_h);
    cudaGetSymbolAddress((void**)&p_g1u,  g_g1u);
    cudaGetSymbolAddress((void**)&p_g2u,  g_g2u);
    cudaGetSymbolAddress((void**)&p_g1i,  g_g1i);
    cudaGetSymbolAddress((void**)&p_g2i,  g_g2i);
    cudaGetSymbolAddress((void**)&p_gcnu, g_gcnu);
    cudaGetSymbolAddress((void**)&p_gcni, g_gcni);
    cudaGetSymbolAddress((void**)&p_acc,  g_acc);
    cudaGetSymbolAddress((void**)&p_rpu,  g_rowptr_u);
    cudaGetSymbolAddress((void**)&p_rpi,  g_rowptr_i);
    cudaGetSymbolAddress((void**)&p_csru, g_csr_u);
    cudaGetSymbolAddress((void**)&p_csri, g_csr_i);

    static cudaStream_t s2 = nullptr;
    static cudaEvent_t evZ, evConv, evScat, evB, evA, ev3i;
    if (!s2) {
        cudaStreamCreateWithFlags(&s2, cudaStreamNonBlocking);
        cudaEventCreateWithFlags(&evZ,    cudaEventDisableTiming);
        cudaEventCreateWithFlags(&evConv, cudaEventDisableTiming);
        cudaEventCreateWithFlags(&evScat, cudaEventDisableTiming);
        cudaEventCreateWithFlags(&evB,    cudaEventDisableTiming);
        cudaEventCreateWithFlags(&evA,    cudaEventDisableTiming);
        cudaEventCreateWithFlags(&ev3i,   cudaEventDisableTiming);
    }

    const int HB = (NEDGE / 4 + 255) / 256;   // hist: 4 edges/thread
    const int SB = (NEDGE / 2 + 255) / 256;   // scatter: 2 edges/thread
    const int UB = (USER_NUM * 32 + 255) / 256;
    const int IB = (ITEM_NUM * 32 + 255) / 256;

    // ---- build phase: CSR chain on main, emb conversion forked on s2 ----
    zero_kernel<<<512, 256>>>();
    cudaEventRecord(evZ, 0);
    cudaStreamWaitEvent(s2, evZ, 0);
    conv_kernel<<<1024, 256, 0, s2>>>(user_emb, item_emb);
    cudaEventRecord(evConv, s2);

    hist_kernel<<<HB, 256>>>(edge_u, edge_i);
    scan_partial2<<<NBU + NBI, 256>>>();
    scan_bsum2<<<1, 64>>>();
    scan_final2<<<NBU + NBI, 256>>>();
    scatter_kernel<<<SB, 256>>>(edge_u, edge_i, edge_val);
    cudaEventRecord(evScat, 0);

    // main waits for conv before chain A
    cudaStreamWaitEvent(0, evConv, 0);

    // ---- chain A (main): g1u <- csr_u x emb_i ; g2i <- csr_i x g1u ----
    spmm_h2h<<<UB, 256>>>(p_rpu, p_csru, p_embi, p_g1u, USER_NUM);
    spmm_h2h<<<IB, 256>>>(p_rpi, p_csri, p_g1u, p_g2i, ITEM_NUM);

    // ---- chain B (s2): g1i <- csr_i x emb_u ; g2u <- csr_u x g1i ----
    cudaStreamWaitEvent(s2, evScat, 0);       // csr ready (conv already in s2 order)
    spmm_h2h<<<IB, 256, 0, s2>>>(p_rpi, p_csri, p_embu, p_g1i, ITEM_NUM);
    spmm_h2h<<<UB, 256, 0, s2>>>(p_rpu, p_csru, p_g1i, p_g2u, USER_NUM);
    cudaEventRecord(evB, s2);                 // chain B complete

    // ---- cross-join, then hop 3 on both streams ----
    cudaEventRecord(evA, 0);                  // chain A complete
    cudaStreamWaitEvent(0, evB, 0);
    cudaStreamWaitEvent(s2, evA, 0);

    spmm3_fused<<<IB, 256, 0, s2>>>(p_rpi, p_csri, p_g2u, item_emb, p_g1i, p_g2i,
                                    old_I, n_I, p_gcni, p_acc + 3, ITEM_NUM);
    cudaEventRecord(ev3i, s2);
    spmm3_fused<<<UB, 256>>>(p_rpu, p_csru, p_g2i, user_emb, p_g1u, p_g2u,
                             old_U, n_U, p_gcnu, p_acc + 2, USER_NUM);
    cudaStreamWaitEvent(0, ev3i, 0);

    bpr_kernel<<<(NB + 7) / 8, 256>>>(user, item_i, item_j);
    finalize_kernel<<<1, 32>>>(out);
}

// round 14
// speedup vs baseline: 1.3617x; 1.3617x over previous
#include <cuda_runtime.h>
#include <cuda_fp16.h>
#include <cstdint>

#define USER_NUM 100000
#define ITEM_NUM 50000
#define DIM      64
#define NEDGE    3200000
#define NB       16384
#define SCAN_CHUNK 4096
#define NBU 25   // ceil(100000/4096)
#define NBI 13   // ceil(50000/4096)

// ---------------- scratch (device globals) ----------------------------------
__device__ __half g_embu_h[USER_NUM * DIM];
__device__ __half g_embi_h[ITEM_NUM * DIM];
__device__ __half g_g1u[USER_NUM * DIM];
__device__ __half g_g2u[USER_NUM * DIM];
__device__ __half g_g1i[ITEM_NUM * DIM];
__device__ __half g_g2i[ITEM_NUM * DIM];
__device__ float  g_gcnu[USER_NUM * DIM];
__device__ float  g_gcni[ITEM_NUM * DIM];

__device__ int  g_cnt_u[USER_NUM];
__device__ int  g_cnt_i[ITEM_NUM];
__device__ int  g_rowptr_u[USER_NUM + 1];
__device__ int  g_rowptr_i[ITEM_NUM + 1];
__device__ int  g_head_u[USER_NUM];
__device__ int  g_head_i[ITEM_NUM];
__device__ int  g_bsum_u[32];
__device__ int  g_bsum_i[32];
__device__ int2 g_csr_u[NEDGE];
__device__ int2 g_csr_i[NEDGE];

// [0]=bpr_sum, [1]=reg_sum, [2]=lossU dot, [3]=lossI dot
__device__ float g_acc[4];

// ---------------- zero counters ----------------------------------------------
__global__ void zero_kernel() {
    int stride = gridDim.x * blockDim.x;
    for (int i = blockIdx.x * blockDim.x + threadIdx.x; i < USER_NUM; i += stride)
        g_cnt_u[i] = 0;
    for (int i = blockIdx.x * blockDim.x + threadIdx.x; i < ITEM_NUM; i += stride)
        g_cnt_i[i] = 0;
    if (blockIdx.x == 0 && threadIdx.x < 4) g_acc[threadIdx.x] = 0.f;
}

// ---------------- convert embeddings to fp16 (side stream) ---------------------
__global__ void conv_kernel(const float* __restrict__ ue, const float* __restrict__ ie) {
    int stride = gridDim.x * blockDim.x;
    const int nu2 = USER_NUM * DIM / 2;
    const int ni2 = ITEM_NUM * DIM / 2;
    for (int i = blockIdx.x * blockDim.x + threadIdx.x; i < nu2; i += stride) {
        float2 f = reinterpret_cast<const float2*>(ue)[i];
        reinterpret_cast<__half2*>(g_embu_h)[i] = __floats2half2_rn(f.x, f.y);
    }
    for (int i = blockIdx.x * blockDim.x + threadIdx.x; i < ni2; i += stride) {
        float2 f = reinterpret_cast<const float2*>(ie)[i];
        reinterpret_cast<__half2*>(g_embi_h)[i] = __floats2half2_rn(f.x, f.y);
    }
}

// ---------------- histogram: int4-vectorized, 4 edges/thread, RED-style --------
__global__ void hist_kernel(const int* __restrict__ eu, const int* __restrict__ ei) {
    int t = blockIdx.x * blockDim.x + threadIdx.x;
    if (t >= NEDGE / 4) return;
    int4 u = __ldg(reinterpret_cast<const int4*>(eu) + t);
    int4 v = __ldg(reinterpret_cast<const int4*>(ei) + t);
    atomicAdd(&g_cnt_u[u.x], 1);
    atomicAdd(&g_cnt_u[u.y], 1);
    atomicAdd(&g_cnt_u[u.z], 1);
    atomicAdd(&g_cnt_u[u.w], 1);
    atomicAdd(&g_cnt_i[v.x], 1);
    atomicAdd(&g_cnt_i[v.y], 1);
    atomicAdd(&g_cnt_i[v.z], 1);
    atomicAdd(&g_cnt_i[v.w], 1);
}

// ---------------- merged 3-phase scan ----------------------------------------------
__global__ void scan_partial2() {
    bool isU = blockIdx.x < NBU;
    const int* __restrict__ cnt = isU ? g_cnt_u : g_cnt_i;
    int* __restrict__ bsum      = isU ? g_bsum_u : g_bsum_i;
    int n = isU ? USER_NUM : ITEM_NUM;
    int b = isU ? blockIdx.x : blockIdx.x - NBU;

    __shared__ int sw[8];
    int t = threadIdx.x;
    int base = b * SCAN_CHUNK;
    int s = 0;
    #pragma unroll
    for (int k = 0; k < 16; k++) {
        int i = base + k * 256 + t;
        if (i < n) s += cnt[i];
    }
    #pragma unroll
    for (int off = 16; off; off >>= 1) s += __shfl_xor_sync(0xffffffffu, s, off);
    if ((t & 31) == 0) sw[t >> 5] = s;
    __syncthreads();
    if (t == 0) {
        int tot = 0;
        #pragma unroll
        for (int k = 0; k < 8; k++) tot += sw[k];
        bsum[b] = tot;
    }
}

__global__ void scan_bsum2() {
    int w = threadIdx.x >> 5, lane = threadIdx.x & 31;
    int* bsum = w ? g_bsum_i : g_bsum_u;
    int nb = w ? NBI : NBU;
    int v = (lane < nb) ? bsum[lane] : 0;
    int incl = v;
    #pragma unroll
    for (int off = 1; off < 32; off <<= 1) {
        int y = __shfl_up_sync(0xffffffffu, incl, off);
        if (lane >= off) incl += y;
    }
    if (lane < nb) bsum[lane] = incl - v;
    if (lane == 0) {
        if (w) g_rowptr_i[ITEM_NUM] = NEDGE; else g_rowptr_u[USER_NUM] = NEDGE;
    }
}

__global__ void scan_final2() {
    bool isU = blockIdx.x < NBU;
    const int* __restrict__ cnt  = isU ? g_cnt_u : g_cnt_i;
    int* __restrict__ rowptr     = isU ? g_rowptr_u : g_rowptr_i;
    int* __restrict__ head       = isU ? g_head_u : g_head_i;
    const int* __restrict__ bsum = isU ? g_bsum_u : g_bsum_i;
    int n = isU ? USER_NUM : ITEM_NUM;
    int b = isU ? blockIdx.x : blockIdx.x - NBU;

    int t = threadIdx.x;
    int base = b * SCAN_CHUNK;
    int idx0 = base + t * 16;
    int v[16];
    int s = 0;
    #pragma unroll
    for (int k = 0; k < 16; k++) {
        int i = idx0 + k;
        v[k] = (i < n) ? cnt[i] : 0;
        s += v[k];
    }
    int lane = t & 31, w = t >> 5;
    int sIncl = s;
    #pragma unroll
    for (int off = 1; off < 32; off <<= 1) {
        int y = __shfl_up_sync(0xffffffffu, sIncl, off);
        if (lane >= off) sIncl += y;
    }
    __shared__ int wsum[8], wpre[8];
    if (lane == 31) wsum[w] = sIncl;
    __syncthreads();
    if (t == 0) {
        int run = 0;
        #pragma unroll
        for (int k = 0; k < 8; k++) { wpre[k] = run; run += wsum[k]; }
    }
    __syncthreads();
    int excl = bsum[b] + wpre[w] + (sIncl - s);
    #pragma unroll
    for (int k = 0; k < 16; k++) {
        int i = idx0 + k;
        if (i < n) { rowptr[i] = excl; head[i] = excl; excl += v[k]; }
    }
}

// ---------------- scatter: 2 edges/thread, atomics batched before stores ----------
__global__ void scatter_kernel(const int* __restrict__ eu, const int* __restrict__ ei,
                               const float* __restrict__ ev) {
    int t = blockIdx.x * blockDim.x + threadIdx.x;
    if (t >= NEDGE / 2) return;
    int2  u  = __ldg(reinterpret_cast<const int2*>(eu) + t);
    int2  it = __ldg(reinterpret_cast<const int2*>(ei) + t);
    float2 v = __ldg(reinterpret_cast<const float2*>(ev) + t);
    int vb0 = __float_as_int(v.x);
    int vb1 = __float_as_int(v.y);
    int pu0 = atomicAdd(&g_head_u[u.x],  1);
    int pu1 = atomicAdd(&g_head_u[u.y],  1);
    int pi0 = atomicAdd(&g_head_i[it.x], 1);
    int pi1 = atomicAdd(&g_head_i[it.y], 1);
    g_csr_u[pu0] = make_int2(it.x, vb0);
    g_csr_u[pu1] = make_int2(it.y, vb1);
    g_csr_i[pi0] = make_int2(u.x,  vb0);
    g_csr_i[pi1] = make_int2(u.y,  vb1);
}

// ---------------- SPMM: half gather -> half out (proven body) ---------------------
__global__ void spmm_h2h(const int* __restrict__ rowptr, const int2* __restrict__ csr,
                         const __half* __restrict__ x, __half* __restrict__ out, int nrows) {
    int row  = (blockIdx.x * blockDim.x + threadIdx.x) >> 5;
    int lane = threadIdx.x & 31;
    int lane16 = lane & 15, hw = lane >> 4;
    if (row >= nrows) return;
    int beg = __ldg(rowptr + row), end = __ldg(rowptr + row + 1);

    float4 acc = make_float4(0.f, 0.f, 0.f, 0.f);
    for (int e = beg + hw; e < end; e += 2) {
        int2 cv = __ldg(csr + e);
        float v = __int_as_float(cv.y);
        uint2 raw = __ldg(reinterpret_cast<const uint2*>(x) + (size_t)cv.x * 16 + lane16);
        float2 f0 = __half22float2(*reinterpret_cast<__half2*>(&raw.x));
        float2 f1 = __half22float2(*reinterpret_cast<__half2*>(&raw.y));
        acc.x = fmaf(v, f0.x, acc.x);
        acc.y = fmaf(v, f0.y, acc.y);
        acc.z = fmaf(v, f1.x, acc.z);
        acc.w = fmaf(v, f1.y, acc.w);
    }
    acc.x += __shfl_xor_sync(0xffffffffu, acc.x, 16);
    acc.y += __shfl_xor_sync(0xffffffffu, acc.y, 16);
    acc.z += __shfl_xor_sync(0xffffffffu, acc.z, 16);
    acc.w += __shfl_xor_sync(0xffffffffu, acc.w, 16);
    if (lane < 16) {
        __half2 h0 = __floats2half2_rn(acc.x, acc.y);
        __half2 h1 = __floats2half2_rn(acc.z, acc.w);
        uint2 pk;
        pk.x = *reinterpret_cast<unsigned*>(&h0);
        pk.y = *reinterpret_cast<unsigned*>(&h1);
        reinterpret_cast<uint2*>(out)[(size_t)row * 16 + lane16] = pk;
    }
}

// ---------------- hop 3 fused: half gather + gcn combine + self-distill -------------
__global__ void spmm3_fused(const int* __restrict__ rowptr, const int2* __restrict__ csr,
                            const __half* __restrict__ xg,
                            const float* __restrict__ emb,
                            const __half* __restrict__ g1,
                            const __half* __restrict__ g2,
                            const float* __restrict__ oldE,
                            const float* __restrict__ nvec,
                            float* __restrict__ gcn,
                            float* __restrict__ accslot,
                            int nrows) {
    int warpInBlk = threadIdx.x >> 5;
    int row  = (blockIdx.x * blockDim.x + threadIdx.x) >> 5;
    int lane = threadIdx.x & 31;
    int lane16 = lane & 15, hw = lane >> 4;

    __shared__ float sm[8];
    float contrib = 0.f;

    if (row < nrows) {
        int beg = __ldg(rowptr + row), end = __ldg(rowptr + row + 1);
        float4 acc = make_float4(0.f, 0.f, 0.f, 0.f);
        for (int e = beg + hw; e < end; e += 2) {
            int2 cv = __ldg(csr + e);
            float v = __int_as_float(cv.y);
            uint2 raw = __ldg(reinterpret_cast<const uint2*>(xg) + (size_t)cv.x * 16 + lane16);
            float2 f0 = __half22float2(*reinterpret_cast<__half2*>(&raw.x));
            float2 f1 = __half22float2(*reinterpret_cast<__half2*>(&raw.y));
            acc.x = fmaf(v, f0.x, acc.x);
            acc.y = fmaf(v, f0.y, acc.y);
            acc.z = fmaf(v, f1.x, acc.z);
            acc.w = fmaf(v, f1.y, acc.w);
        }
        acc.x += __shfl_xor_sync(0xffffffffu, acc.x, 16);
        acc.y += __shfl_xor_sync(0xffffffffu, acc.y, 16);
        acc.z += __shfl_xor_sync(0xffffffffu, acc.z, 16);
        acc.w += __shfl_xor_sync(0xffffffffu, acc.w, 16);

        float sq = 0.f;
        if (lane < 16) {
            size_t rb = (size_t)row * DIM;
            float4 ee = __ldg(reinterpret_cast<const float4*>(emb + rb) + lane16);
            uint2 r1 = __ldg(reinterpret_cast<const uint2*>(g1) + (size_t)row * 16 + lane16);
            uint2 r2 = __ldg(reinterpret_cast<const uint2*>(g2) + (size_t)row * 16 + lane16);
            float2 g1a = __half22float2(*reinterpret_cast<__half2*>(&r1.x));
            float2 g1b = __half22float2(*reinterpret_cast<__half2*>(&r1.y));
            float2 g2a = __half22float2(*reinterpret_cast<__half2*>(&r2.x));
            float2 g2b = __half22float2(*reinterpret_cast<__half2*>(&r2.y));
            const float c2 = 1.f / 3.f;
            float4 gv;
            gv.x = ee.x + 0.5f * g1a.x + c2 * g2a.x + 0.25f * acc.x;
            gv.y = ee.y + 0.5f * g1a.y + c2 * g2a.y + 0.25f * acc.y;
            gv.z = ee.z + 0.5f * g1b.x + c2 * g2b.x + 0.25f * acc.z;
            gv.w = ee.w + 0.5f * g1b.y + c2 * g2b.y + 0.25f * acc.w;
            reinterpret_cast<float4*>(gcn + rb)[lane16] = gv;

            float4 ov = __ldg(reinterpret_cast<const float4*>(oldE + rb) + lane16);
            float dx = ov.x - gv.x, dy = ov.y - gv.y, dz = ov.z - gv.z, dw = ov.w - gv.w;
            sq = dx * dx + dy * dy + dz * dz + dw * dw;
        }
        #pragma unroll
        for (int off = 16; off; off >>= 1) sq += __shfl_xor_sync(0xffffffffu, sq, off);
        if (lane == 0) contrib = sqrtf(sq) * __ldg(nvec + row);
    }

    if (lane == 0) sm[warpInBlk] = contrib;
    __syncthreads();
    if (threadIdx.x == 0) {
        float v = 0.f;
        #pragma unroll
        for (int k = 0; k < 8; k++) v += sm[k];
        atomicAdd(accslot, v);
    }
}

// ---------------- BPR loss ---------------------------------------------------------
__global__ void bpr_kernel(const int* __restrict__ user,
                           const int* __restrict__ iti,
                           const int* __restrict__ itj) {
    int warp = threadIdx.x >> 5;
    int lane = threadIdx.x & 31;
    int b = blockIdx.x * 8 + warp;

    float lbpr = 0.f, lreg = 0.f;
    if (b < NB) {
        int uu = user[b], a = iti[b], c = itj[b];
        float2 u2 = reinterpret_cast<const float2*>(g_gcnu + (size_t)uu * DIM)[lane];
        float2 x1 = reinterpret_cast<const float2*>(g_gcni + (size_t)a  * DIM)[lane];
        float2 x2 = reinterpret_cast<const float2*>(g_gcni + (size_t)c  * DIM)[lane];
        float pi = u2.x * x1.x + u2.y * x1.y;
        float pj = u2.x * x2.x + u2.y * x2.y;
        float rg = u2.x * u2.x + u2.y * u2.y
                 + x1.x * x1.x + x1.y * x1.y
                 + x2.x * x2.x + x2.y * x2.y;
        #pragma unroll
        for (int off = 16; off; off >>= 1) {
            pi += __shfl_xor_sync(0xffffffffu, pi, off);
            pj += __shfl_xor_sync(0xffffffffu, pj, off);
            rg += __shfl_xor_sync(0xffffffffu, rg, off);
        }
        if (lane == 0) {
            float x = pi - pj;
            lbpr = fmaxf(-x, 0.f) + log1pf(expf(-fabsf(x)));
            lreg = rg;
        }
    }
    __shared__ float s1[8], s2[8];
    if (lane == 0) { s1[warp] = lbpr; s2[warp] = lreg; }
    __syncthreads();
    if (threadIdx.x == 0) {
        float a = 0.f, r = 0.f;
        #pragma unroll
        for (int k = 0; k < 8; k++) { a += s1[k]; r += s2[k]; }
        atomicAdd(&g_acc[0], a);
        atomicAdd(&g_acc[1], r);
    }
}

// ---------------- finalize -------------------------------------------------------------
__global__ void finalize_kernel(float* __restrict__ out) {
    if (threadIdx.x == 0) {
        float bpr = g_acc[0] / (float)NB;
        float reg = 1e-4f * (g_acc[1] / (float)NB);
        float ls  = g_acc[2] / (float)USER_NUM + g_acc[3] / (float)ITEM_NUM;
        out[0] = bpr + reg;
        out[1] = 100.f * ls;
        out[2] = 1.f;
        out[3] = 1.f;
    }
}

// ---------------- launch ------------------------------------------------------------------
extern "C" void kernel_launch(void* const* d_in, const int* in_sizes, int n_in,
                              void* d_out, int out_size) {
    const int*   user     = (const int*)d_in[0];
    const int*   item_i   = (const int*)d_in[1];
    const int*   item_j   = (const int*)d_in[2];
    const int*   edge_u   = (const int*)d_in[3];
    const int*   edge_i   = (const int*)d_in[4];
    const float* edge_val = (const float*)d_in[5];
    const float* user_emb = (const float*)d_in[6];
    const float* item_emb = (const float*)d_in[7];
    const float* old_U    = (const float*)d_in[8];
    const float* old_I    = (const float*)d_in[9];
    const float* n_U      = (const float*)d_in[10];
    const float* n_I      = (const float*)d_in[11];
    float* out = (float*)d_out;

    __half *p_embu, *p_embi, *p_g1u, *p_g2u, *p_g1i, *p_g2i;
    float  *p_gcnu, *p_gcni, *p_acc;
    int    *p_rpu, *p_rpi;
    int2   *p_csru, *p_csri;
    cudaGetSymbolAddress((void**)&p_embu, g_embu_h);
    cudaGetSymbolAddress((void**)&p_embi, g_embi_h);
    cudaGetSymbolAddress((void**)&p_g1u,  g_g1u);
    cudaGetSymbolAddress((void**)&p_g2u,  g_g2u);
    cudaGetSymbolAddress((void**)&p_g1i,  g_g1i);
    cudaGetSymbolAddress((void**)&p_g2i,  g_g2i);
    cudaGetSymbolAddress((void**)&p_gcnu, g_gcnu);
    cudaGetSymbolAddress((void**)&p_gcni, g_gcni);
    cudaGetSymbolAddress((void**)&p_acc,  g_acc);
    cudaGetSymbolAddress((void**)&p_rpu,  g_rowptr_u);
    cudaGetSymbolAddress((void**)&p_rpi,  g_rowptr_i);
    cudaGetSymbolAddress((void**)&p_csru, g_csr_u);
    cudaGetSymbolAddress((void**)&p_csri, g_csr_i);

    static cudaStream_t s2 = nullptr;
    static cudaEvent_t evZ, evConv, evScat, evB, evA, ev3i;
    if (!s2) {
        cudaStreamCreateWithFlags(&s2, cudaStreamNonBlocking);
        cudaEventCreateWithFlags(&evZ,    cudaEventDisableTiming);
        cudaEventCreateWithFlags(&evConv, cudaEventDisableTiming);
        cudaEventCreateWithFlags(&evScat, cudaEventDisableTiming);
        cudaEventCreateWithFlags(&evB,    cudaEventDisableTiming);
        cudaEventCreateWithFlags(&evA,    cudaEventDisableTiming);
        cudaEventCreateWithFlags(&ev3i,   cudaEventDisableTiming);
    }

    const int HB = (NEDGE / 4 + 255) / 256;   // hist: 4 edges/thread
    const int SB = (NEDGE / 2 + 255) / 256;   // scatter: 2 edges/thread
    const int UB = (USER_NUM * 32 + 255) / 256;
    const int IB = (ITEM_NUM * 32 + 255) / 256;

    // ---- build phase: CSR chain on main stream, emb conversion forked on s2 ----
    zero_kernel<<<512, 256>>>();
    cudaEventRecord(evZ, 0);
    cudaStreamWaitEvent(s2, evZ, 0);
    conv_kernel<<<1024, 256, 0, s2>>>(user_emb, item_emb);
    cudaEventRecord(evConv, s2);

    hist_kernel<<<HB, 256>>>(edge_u, edge_i);
    scan_partial2<<<NBU + NBI, 256>>>();
    scan_bsum2<<<1, 64>>>();
    scan_final2<<<NBU + NBI, 256>>>();
    scatter_kernel<<<SB, 256>>>(edge_u, edge_i, edge_val);
    cudaEventRecord(evScat, 0);

    // main waits for conv before chain A
    cudaStreamWaitEvent(0, evConv, 0);

    // ---- chain A (main): g1u <- csr_u x emb_i ; g2i <- csr_i x g1u ----
    spmm_h2h<<<UB, 256>>>(p_rpu, p_csru, p_embi, p_g1u, USER_NUM);
    spmm_h2h<<<IB, 256>>>(p_rpi, p_csri, p_g1u, p_g2i, ITEM_NUM);

    // ---- chain B (s2): g1i <- csr_i x emb_u ; g2u <- csr_u x g1i ----
    cudaStreamWaitEvent(s2, evScat, 0);       // csr ready (conv already in s2 order)
    spmm_h2h<<<IB, 256, 0, s2>>>(p_rpi, p_csri, p_embu, p_g1i, ITEM_NUM);
    spmm_h2h<<<UB, 256, 0, s2>>>(p_rpu, p_csru, p_g1i, p_g2u, USER_NUM);
    cudaEventRecord(evB, s2);                 // chain B complete

    // ---- cross-join, then hop 3 on both streams ----
    cudaEventRecord(evA, 0);                  // chain A complete
    cudaStreamWaitEvent(0, evB, 0);
    cudaStreamWaitEvent(s2, evA, 0);

    spmm3_fused<<<IB, 256, 0, s2>>>(p_rpi, p_csri, p_g2u, item_emb, p_g1i, p_g2i,
                                    old_I, n_I, p_gcni, p_acc + 3, ITEM_NUM);
    cudaEventRecord(ev3i, s2);
    spmm3_fused<<<UB, 256>>>(p_rpu, p_csru, p_g2i, user_emb, p_g1u, p_g2u,
                             old_U, n_U, p_gcnu, p_acc + 2, USER_NUM);
    cudaStreamWaitEvent(0, ev3i, 0);

    bpr_kernel<<<(NB + 7) / 8, 256>>>(user, item_i, item_j);
    finalize_kernel<<<1, 32>>>(out);
}

// round 15
// speedup vs baseline: 1.3661x; 1.0032x over previous
#include <cuda_runtime.h>
#include <cuda_fp16.h>
#include <cstdint>

#define USER_NUM 100000
#define ITEM_NUM 50000
#define DIM      64
#define NEDGE    3200000
#define NB       16384
#define SCAN_CHUNK 4096
#define NBU 25   // ceil(100000/4096)
#define NBI 13   // ceil(50000/4096)

// ---------------- scratch (device globals) ----------------------------------
__device__ __half g_embu_h[USER_NUM * DIM];
__device__ __half g_embi_h[ITEM_NUM * DIM];
__device__ __half g_g1u[USER_NUM * DIM];
__device__ __half g_g2u[USER_NUM * DIM];
__device__ __half g_g1i[ITEM_NUM * DIM];
__device__ __half g_g2i[ITEM_NUM * DIM];
__device__ __half g_gcnu[USER_NUM * DIM];   // fp16 now (bpr-only consumer)
__device__ __half g_gcni[ITEM_NUM * DIM];

__device__ int  g_cnt_u[USER_NUM];
__device__ int  g_cnt_i[ITEM_NUM];
__device__ int  g_rowptr_u[USER_NUM + 1];
__device__ int  g_rowptr_i[ITEM_NUM + 1];
__device__ int  g_head_u[USER_NUM];
__device__ int  g_head_i[ITEM_NUM];
__device__ int  g_bsum_u[32];
__device__ int  g_bsum_i[32];
__device__ int2 g_csr_u[NEDGE];
__device__ int2 g_csr_i[NEDGE];

// [0]=bpr_sum, [1]=reg_sum, [2]=lossU dot, [3]=lossI dot
__device__ float g_acc[4];

// ---------------- zero counters ----------------------------------------------
__global__ void zero_kernel() {
    int stride = gridDim.x * blockDim.x;
    for (int i = blockIdx.x * blockDim.x + threadIdx.x; i < USER_NUM; i += stride)
        g_cnt_u[i] = 0;
    for (int i = blockIdx.x * blockDim.x + threadIdx.x; i < ITEM_NUM; i += stride)
        g_cnt_i[i] = 0;
    if (blockIdx.x == 0 && threadIdx.x < 4) g_acc[threadIdx.x] = 0.f;
}

// ---------------- convert embeddings to fp16 (side stream) ---------------------
__global__ void conv_kernel(const float* __restrict__ ue, const float* __restrict__ ie) {
    int stride = gridDim.x * blockDim.x;
    const int nu2 = USER_NUM * DIM / 2;
    const int ni2 = ITEM_NUM * DIM / 2;
    for (int i = blockIdx.x * blockDim.x + threadIdx.x; i < nu2; i += stride) {
        float2 f = reinterpret_cast<const float2*>(ue)[i];
        reinterpret_cast<__half2*>(g_embu_h)[i] = __floats2half2_rn(f.x, f.y);
    }
    for (int i = blockIdx.x * blockDim.x + threadIdx.x; i < ni2; i += stride) {
        float2 f = reinterpret_cast<const float2*>(ie)[i];
        reinterpret_cast<__half2*>(g_embi_h)[i] = __floats2half2_rn(f.x, f.y);
    }
}

// ---------------- histogram: int4-vectorized, 4 edges/thread, RED-style --------
__global__ void hist_kernel(const int* __restrict__ eu, const int* __restrict__ ei) {
    int t = blockIdx.x * blockDim.x + threadIdx.x;
    if (t >= NEDGE / 4) return;
    int4 u = __ldg(reinterpret_cast<const int4*>(eu) + t);
    int4 v = __ldg(reinterpret_cast<const int4*>(ei) + t);
    atomicAdd(&g_cnt_u[u.x], 1);
    atomicAdd(&g_cnt_u[u.y], 1);
    atomicAdd(&g_cnt_u[u.z], 1);
    atomicAdd(&g_cnt_u[u.w], 1);
    atomicAdd(&g_cnt_i[v.x], 1);
    atomicAdd(&g_cnt_i[v.y], 1);
    atomicAdd(&g_cnt_i[v.z], 1);
    atomicAdd(&g_cnt_i[v.w], 1);
}

// ---------------- merged 3-phase scan ----------------------------------------------
__global__ void scan_partial2() {
    bool isU = blockIdx.x < NBU;
    const int* __restrict__ cnt = isU ? g_cnt_u : g_cnt_i;
    int* __restrict__ bsum      = isU ? g_bsum_u : g_bsum_i;
    int n = isU ? USER_NUM : ITEM_NUM;
    int b = isU ? blockIdx.x : blockIdx.x - NBU;

    __shared__ int sw[8];
    int t = threadIdx.x;
    int base = b * SCAN_CHUNK;
    int s = 0;
    #pragma unroll
    for (int k = 0; k < 16; k++) {
        int i = base + k * 256 + t;
        if (i < n) s += cnt[i];
    }
    #pragma unroll
    for (int off = 16; off; off >>= 1) s += __shfl_xor_sync(0xffffffffu, s, off);
    if ((t & 31) == 0) sw[t >> 5] = s;
    __syncthreads();
    if (t == 0) {
        int tot = 0;
        #pragma unroll
        for (int k = 0; k < 8; k++) tot += sw[k];
        bsum[b] = tot;
    }
}

__global__ void scan_bsum2() {
    int w = threadIdx.x >> 5, lane = threadIdx.x & 31;
    int* bsum = w ? g_bsum_i : g_bsum_u;
    int nb = w ? NBI : NBU;
    int v = (lane < nb) ? bsum[lane] : 0;
    int incl = v;
    #pragma unroll
    for (int off = 1; off < 32; off <<= 1) {
        int y = __shfl_up_sync(0xffffffffu, incl, off);
        if (lane >= off) incl += y;
    }
    if (lane < nb) bsum[lane] = incl - v;
    if (lane == 0) {
        if (w) g_rowptr_i[ITEM_NUM] = NEDGE; else g_rowptr_u[USER_NUM] = NEDGE;
    }
}

__global__ void scan_final2() {
    bool isU = blockIdx.x < NBU;
    const int* __restrict__ cnt  = isU ? g_cnt_u : g_cnt_i;
    int* __restrict__ rowptr     = isU ? g_rowptr_u : g_rowptr_i;
    int* __restrict__ head       = isU ? g_head_u : g_head_i;
    const int* __restrict__ bsum = isU ? g_bsum_u : g_bsum_i;
    int n = isU ? USER_NUM : ITEM_NUM;
    int b = isU ? blockIdx.x : blockIdx.x - NBU;

    int t = threadIdx.x;
    int base = b * SCAN_CHUNK;
    int idx0 = base + t * 16;
    int v[16];
    int s = 0;
    #pragma unroll
    for (int k = 0; k < 16; k++) {
        int i = idx0 + k;
        v[k] = (i < n) ? cnt[i] : 0;
        s += v[k];
    }
    int lane = t & 31, w = t >> 5;
    int sIncl = s;
    #pragma unroll
    for (int off = 1; off < 32; off <<= 1) {
        int y = __shfl_up_sync(0xffffffffu, sIncl, off);
        if (lane >= off) sIncl += y;
    }
    __shared__ int wsum[8], wpre[8];
    if (lane == 31) wsum[w] = sIncl;
    __syncthreads();
    if (t == 0) {
        int run = 0;
        #pragma unroll
        for (int k = 0; k < 8; k++) { wpre[k] = run; run += wsum[k]; }
    }
    __syncthreads();
    int excl = bsum[b] + wpre[w] + (sIncl - s);
    #pragma unroll
    for (int k = 0; k < 16; k++) {
        int i = idx0 + k;
        if (i < n) { rowptr[i] = excl; head[i] = excl; excl += v[k]; }
    }
}

// ---------------- scatter: 2 edges/thread, atomics batched before stores ----------
__global__ void scatter_kernel(const int* __restrict__ eu, const int* __restrict__ ei,
                               const float* __restrict__ ev) {
    int t = blockIdx.x * blockDim.x + threadIdx.x;
    if (t >= NEDGE / 2) return;
    int2  u  = __ldg(reinterpret_cast<const int2*>(eu) + t);
    int2  it = __ldg(reinterpret_cast<const int2*>(ei) + t);
    float2 v = __ldg(reinterpret_cast<const float2*>(ev) + t);
    int vb0 = __float_as_int(v.x);
    int vb1 = __float_as_int(v.y);
    int pu0 = atomicAdd(&g_head_u[u.x],  1);
    int pu1 = atomicAdd(&g_head_u[u.y],  1);
    int pi0 = atomicAdd(&g_head_i[it.x], 1);
    int pi1 = atomicAdd(&g_head_i[it.y], 1);
    g_csr_u[pu0] = make_int2(it.x, vb0);
    g_csr_u[pu1] = make_int2(it.y, vb1);
    g_csr_i[pi0] = make_int2(u.x,  vb0);
    g_csr_i[pi1] = make_int2(u.y,  vb1);
}

// ---------------- SPMM: half gather -> half out (proven body) ---------------------
__global__ void spmm_h2h(const int* __restrict__ rowptr, const int2* __restrict__ csr,
                         const __half* __restrict__ x, __half* __restrict__ out, int nrows) {
    int row  = (blockIdx.x * blockDim.x + threadIdx.x) >> 5;
    int lane = threadIdx.x & 31;
    int lane16 = lane & 15, hw = lane >> 4;
    if (row >= nrows) return;
    int beg = __ldg(rowptr + row), end = __ldg(rowptr + row + 1);

    float4 acc = make_float4(0.f, 0.f, 0.f, 0.f);
    for (int e = beg + hw; e < end; e += 2) {
        int2 cv = __ldg(csr + e);
        float v = __int_as_float(cv.y);
        uint2 raw = __ldg(reinterpret_cast<const uint2*>(x) + (size_t)cv.x * 16 + lane16);
        float2 f0 = __half22float2(*reinterpret_cast<__half2*>(&raw.x));
        float2 f1 = __half22float2(*reinterpret_cast<__half2*>(&raw.y));
        acc.x = fmaf(v, f0.x, acc.x);
        acc.y = fmaf(v, f0.y, acc.y);
        acc.z = fmaf(v, f1.x, acc.z);
        acc.w = fmaf(v, f1.y, acc.w);
    }
    acc.x += __shfl_xor_sync(0xffffffffu, acc.x, 16);
    acc.y += __shfl_xor_sync(0xffffffffu, acc.y, 16);
    acc.z += __shfl_xor_sync(0xffffffffu, acc.z, 16);
    acc.w += __shfl_xor_sync(0xffffffffu, acc.w, 16);
    if (lane < 16) {
        __half2 h0 = __floats2half2_rn(acc.x, acc.y);
        __half2 h1 = __floats2half2_rn(acc.z, acc.w);
        uint2 pk;
        pk.x = *reinterpret_cast<unsigned*>(&h0);
        pk.y = *reinterpret_cast<unsigned*>(&h1);
        reinterpret_cast<uint2*>(out)[(size_t)row * 16 + lane16] = pk;
    }
}

// ---------------- hop 3 fused: fp16 emb read, fp16 gcn write, fp32 distill ---------
__global__ void spmm3_fused(const int* __restrict__ rowptr, const int2* __restrict__ csr,
                            const __half* __restrict__ xg,
                            const __half* __restrict__ embh,
                            const __half* __restrict__ g1,
                            const __half* __restrict__ g2,
                            const float* __restrict__ oldE,
                            const float* __restrict__ nvec,
                            __half* __restrict__ gcn,
                            float* __restrict__ accslot,
                            int nrows) {
    int warpInBlk = threadIdx.x >> 5;
    int row  = (blockIdx.x * blockDim.x + threadIdx.x) >> 5;
    int lane = threadIdx.x & 31;
    int lane16 = lane & 15, hw = lane >> 4;

    __shared__ float sm[8];
    float contrib = 0.f;

    if (row < nrows) {
        int beg = __ldg(rowptr + row), end = __ldg(rowptr + row + 1);
        float4 acc = make_float4(0.f, 0.f, 0.f, 0.f);
        for (int e = beg + hw; e < end; e += 2) {
            int2 cv = __ldg(csr + e);
            float v = __int_as_float(cv.y);
            uint2 raw = __ldg(reinterpret_cast<const uint2*>(xg) + (size_t)cv.x * 16 + lane16);
            float2 f0 = __half22float2(*reinterpret_cast<__half2*>(&raw.x));
            float2 f1 = __half22float2(*reinterpret_cast<__half2*>(&raw.y));
            acc.x = fmaf(v, f0.x, acc.x);
            acc.y = fmaf(v, f0.y, acc.y);
            acc.z = fmaf(v, f1.x, acc.z);
            acc.w = fmaf(v, f1.y, acc.w);
        }
        acc.x += __shfl_xor_sync(0xffffffffu, acc.x, 16);
        acc.y += __shfl_xor_sync(0xffffffffu, acc.y, 16);
        acc.z += __shfl_xor_sync(0xffffffffu, acc.z, 16);
        acc.w += __shfl_xor_sync(0xffffffffu, acc.w, 16);

        float sq = 0.f;
        if (lane < 16) {
            size_t rb = (size_t)row * DIM;
            uint2 re = __ldg(reinterpret_cast<const uint2*>(embh) + (size_t)row * 16 + lane16);
            uint2 r1 = __ldg(reinterpret_cast<const uint2*>(g1)   + (size_t)row * 16 + lane16);
            uint2 r2 = __ldg(reinterpret_cast<const uint2*>(g2)   + (size_t)row * 16 + lane16);
            float2 e0 = __half22float2(*reinterpret_cast<__half2*>(&re.x));
            float2 e1 = __half22float2(*reinterpret_cast<__half2*>(&re.y));
            float2 g1a = __half22float2(*reinterpret_cast<__half2*>(&r1.x));
            float2 g1b = __half22float2(*reinterpret_cast<__half2*>(&r1.y));
            float2 g2a = __half22float2(*reinterpret_cast<__half2*>(&r2.x));
            float2 g2b = __half22float2(*reinterpret_cast<__half2*>(&r2.y));
            const float c2 = 1.f / 3.f;
            float4 gv;
            gv.x = e0.x + 0.5f * g1a.x + c2 * g2a.x + 0.25f * acc.x;
            gv.y = e0.y + 0.5f * g1a.y + c2 * g2a.y + 0.25f * acc.y;
            gv.z = e1.x + 0.5f * g1b.x + c2 * g2b.x + 0.25f * acc.z;
            gv.w = e1.y + 0.5f * g1b.y + c2 * g2b.y + 0.25f * acc.w;

            // store gcn as fp16 (bpr-only consumer)
            __half2 h0 = __floats2half2_rn(gv.x, gv.y);
            __half2 h1 = __floats2half2_rn(gv.z, gv.w);
            uint2 pk;
            pk.x = *reinterpret_cast<unsigned*>(&h0);
            pk.y = *reinterpret_cast<unsigned*>(&h1);
            reinterpret_cast<uint2*>(gcn)[(size_t)row * 16 + lane16] = pk;

            // self-distill in fp32 (unchanged precision)
            float4 ov = __ldg(reinterpret_cast<const float4*>(oldE + rb) + lane16);
            float dx = ov.x - gv.x, dy = ov.y - gv.y, dz = ov.z - gv.z, dw = ov.w - gv.w;
            sq = dx * dx + dy * dy + dz * dz + dw * dw;
        }
        #pragma unroll
        for (int off = 16; off; off >>= 1) sq += __shfl_xor_sync(0xffffffffu, sq, off);
        if (lane == 0) contrib = sqrtf(sq) * __ldg(nvec + row);
    }

    if (lane == 0) sm[warpInBlk] = contrib;
    __syncthreads();
    if (threadIdx.x == 0) {
        float v = 0.f;
        #pragma unroll
        for (int k = 0; k < 8; k++) v += sm[k];
        atomicAdd(accslot, v);
    }
}

// ---------------- BPR loss (fp16 gcn reads) ----------------------------------------
__global__ void bpr_kernel(const int* __restrict__ user,
                           const int* __restrict__ iti,
                           const int* __restrict__ itj) {
    int warp = threadIdx.x >> 5;
    int lane = threadIdx.x & 31;
    int b = blockIdx.x * 8 + warp;

    float lbpr = 0.f, lreg = 0.f;
    if (b < NB) {
        int uu = user[b], a = iti[b], c = itj[b];
        unsigned ru = __ldg(reinterpret_cast<const unsigned*>(g_gcnu) + (size_t)uu * 32 + lane);
        unsigned r1 = __ldg(reinterpret_cast<const unsigned*>(g_gcni) + (size_t)a  * 32 + lane);
        unsigned r2 = __ldg(reinterpret_cast<const unsigned*>(g_gcni) + (size_t)c  * 32 + lane);
        float2 u2 = __half22float2(*reinterpret_cast<__half2*>(&ru));
        float2 x1 = __half22float2(*reinterpret_cast<__half2*>(&r1));
        float2 x2 = __half22float2(*reinterpret_cast<__half2*>(&r2));
        float pi = u2.x * x1.x + u2.y * x1.y;
        float pj = u2.x * x2.x + u2.y * x2.y;
        float rg = u2.x * u2.x + u2.y * u2.y
                 + x1.x * x1.x + x1.y * x1.y
                 + x2.x * x2.x + x2.y * x2.y;
        #pragma unroll
        for (int off = 16; off; off >>= 1) {
            pi += __shfl_xor_sync(0xffffffffu, pi, off);
            pj += __shfl_xor_sync(0xffffffffu, pj, off);
            rg += __shfl_xor_sync(0xffffffffu, rg, off);
        }
        if (lane == 0) {
            float x = pi - pj;
            lbpr = fmaxf(-x, 0.f) + log1pf(expf(-fabsf(x)));
            lreg = rg;
        }
    }
    __shared__ float s1[8], s2[8];
    if (lane == 0) { s1[warp] = lbpr; s2[warp] = lreg; }
    __syncthreads();
    if (threadIdx.x == 0) {
        float a = 0.f, r = 0.f;
        #pragma unroll
        for (int k = 0; k < 8; k++) { a += s1[k]; r += s2[k]; }
        atomicAdd(&g_acc[0], a);
        atomicAdd(&g_acc[1], r);
    }
}

// ---------------- finalize -------------------------------------------------------------
__global__ void finalize_kernel(float* __restrict__ out) {
    if (threadIdx.x == 0) {
        float bpr = g_acc[0] / (float)NB;
        float reg = 1e-4f * (g_acc[1] / (float)NB);
        float ls  = g_acc[2] / (float)USER_NUM + g_acc[3] / (float)ITEM_NUM;
        out[0] = bpr + reg;
        out[1] = 100.f * ls;
        out[2] = 1.f;
        out[3] = 1.f;
    }
}

// ---------------- launch ------------------------------------------------------------------
extern "C" void kernel_launch(void* const* d_in, const int* in_sizes, int n_in,
                              void* d_out, int out_size) {
    const int*   user     = (const int*)d_in[0];
    const int*   item_i   = (const int*)d_in[1];
    const int*   item_j   = (const int*)d_in[2];
    const int*   edge_u   = (const int*)d_in[3];
    const int*   edge_i   = (const int*)d_in[4];
    const float* edge_val = (const float*)d_in[5];
    const float* user_emb = (const float*)d_in[6];
    const float* item_emb = (const float*)d_in[7];
    const float* old_U    = (const float*)d_in[8];
    const float* old_I    = (const float*)d_in[9];
    const float* n_U      = (const float*)d_in[10];
    const float* n_I      = (const float*)d_in[11];
    float* out = (float*)d_out;

    __half *p_embu, *p_embi, *p_g1u, *p_g2u, *p_g1i, *p_g2i, *p_gcnu, *p_gcni;
    float  *p_acc;
    int    *p_rpu, *p_rpi;
    int2   *p_csru, *p_csri;
    cudaGetSymbolAddress((void**)&p_embu, g_embu_h);
    cudaGetSymbolAddress((void**)&p_embi, g_embi_h);
    cudaGetSymbolAddress((void**)&p_g1u,  g_g1u);
    cudaGetSymbolAddress((void**)&p_g2u,  g_g2u);
    cudaGetSymbolAddress((void**)&p_g1i,  g_g1i);
    cudaGetSymbolAddress((void**)&p_g2i,  g_g2i);
    cudaGetSymbolAddress((void**)&p_gcnu, g_gcnu);
    cudaGetSymbolAddress((void**)&p_gcni, g_gcni);
    cudaGetSymbolAddress((void**)&p_acc,  g_acc);
    cudaGetSymbolAddress((void**)&p_rpu,  g_rowptr_u);
    cudaGetSymbolAddress((void**)&p_rpi,  g_rowptr_i);
    cudaGetSymbolAddress((void**)&p_csru, g_csr_u);
    cudaGetSymbolAddress((void**)&p_csri, g_csr_i);

    static cudaStream_t s2 = nullptr;
    static cudaEvent_t evZ, evConv, evScat, evB, evA, ev3i;
    if (!s2) {
        cudaStreamCreateWithFlags(&s2, cudaStreamNonBlocking);
        cudaEventCreateWithFlags(&evZ,    cudaEventDisableTiming);
        cudaEventCreateWithFlags(&evConv, cudaEventDisableTiming);
        cudaEventCreateWithFlags(&evScat, cudaEventDisableTiming);
        cudaEventCreateWithFlags(&evB,    cudaEventDisableTiming);
        cudaEventCreateWithFlags(&evA,    cudaEventDisableTiming);
        cudaEventCreateWithFlags(&ev3i,   cudaEventDisableTiming);
    }

    const int HB = (NEDGE / 4 + 255) / 256;   // hist: 4 edges/thread
    const int SB = (NEDGE / 2 + 255) / 256;   // scatter: 2 edges/thread
    const int UB = (USER_NUM * 32 + 255) / 256;
    const int IB = (ITEM_NUM * 32 + 255) / 256;

    // ---- build phase: CSR chain on main stream, emb conversion forked on s2 ----
    zero_kernel<<<512, 256>>>();
    cudaEventRecord(evZ, 0);
    cudaStreamWaitEvent(s2, evZ, 0);
    conv_kernel<<<1024, 256, 0, s2>>>(user_emb, item_emb);
    cudaEventRecord(evConv, s2);

    hist_kernel<<<HB, 256>>>(edge_u, edge_i);
    scan_partial2<<<NBU + NBI, 256>>>();
    scan_bsum2<<<1, 64>>>();
    scan_final2<<<NBU + NBI, 256>>>();
    scatter_kernel<<<SB, 256>>>(edge_u, edge_i, edge_val);
    cudaEventRecord(evScat, 0);

    // main waits for conv before chain A
    cudaStreamWaitEvent(0, evConv, 0);

    // ---- chain A (main): g1u <- csr_u x emb_i ; g2i <- csr_i x g1u ----
    spmm_h2h<<<UB, 256>>>(p_rpu, p_csru, p_embi, p_g1u, USER_NUM);
    spmm_h2h<<<IB, 256>>>(p_rpi, p_csri, p_g1u, p_g2i, ITEM_NUM);

    // ---- chain B (s2): g1i <- csr_i x emb_u ; g2u <- csr_u x g1i ----
    cudaStreamWaitEvent(s2, evScat, 0);       // csr ready (conv already in s2 order)
    spmm_h2h<<<IB, 256, 0, s2>>>(p_rpi, p_csri, p_embu, p_g1i, ITEM_NUM);
    spmm_h2h<<<UB, 256, 0, s2>>>(p_rpu, p_csru, p_g1i, p_g2u, USER_NUM);
    cudaEventRecord(evB, s2);                 // chain B complete

    // ---- cross-join, then hop 3 on both streams ----
    cudaEventRecord(evA, 0);                  // chain A complete
    cudaStreamWaitEvent(0, evB, 0);
    cudaStreamWaitEvent(s2, evA, 0);

    spmm3_fused<<<IB, 256, 0, s2>>>(p_rpi, p_csri, p_g2u, p_embi, p_g1i, p_g2i,
                                    old_I, n_I, p_gcni, p_acc + 3, ITEM_NUM);
    cudaEventRecord(ev3i, s2);
    spmm3_fused<<<UB, 256>>>(p_rpu, p_csru, p_g2i, p_embu, p_g1u, p_g2u,
                             old_U, n_U, p_gcnu, p_acc + 2, USER_NUM);
    cudaStreamWaitEvent(0, ev3i, 0);

    bpr_kernel<<<(NB + 7) / 8, 256>>>(user, item_i, item_j);
    finalize_kernel<<<1, 32>>>(out);
}